// round 7
// baseline (speedup 1.0000x reference)
#include <cuda_runtime.h>
#include <math.h>
#include <stddef.h>

// MLA shapes (compile-time constants)
#define B_    2
#define S_    2048
#define H_    2048
#define NH_   16
#define QL_   1536
#define KVL_  512
#define NOPE_ 128
#define ROPE_ 64
#define VD_   128
#define QKH_  192
#define ROWS_ (B_*S_)   // 4096

// ---------------- scratch (device globals: no allocs allowed) ----------------
__device__ float g_qa  [(size_t)ROWS_*QL_];            // x @ wq_a^T (+norm, in-place)
__device__ float g_q   [(size_t)ROWS_*NH_*QKH_];       // q after wq_b + rope  [4096,3072]
__device__ float g_kvf [(size_t)ROWS_*(KVL_+ROPE_)];   // x @ wkv_a^T          [4096,576]
__device__ float g_kvn [(size_t)ROWS_*KVL_];           // rmsnorm(kv)          [4096,512]
__device__ float g_kpe [(size_t)ROWS_*ROPE_];          // roped k_pe           [4096,64]
__device__ float g_kvab[(size_t)B_*NH_*S_*256];        // [b*16+h][t][0:128]=k_abs, [128:256]=v_abs
__device__ float g_att [(size_t)ROWS_*NH_*VD_];        // attention out        [4096,2048]
__device__ float g_cos [(size_t)S_*ROPE_];
__device__ float g_sin [(size_t)S_*ROPE_];

// ---------------- generic SGEMM: C = A(MxK) @ W(NxK)^T + bias ----------------
// 128x128 tile, BK=16, 256 threads, 8x8 per-thread microtile.
// z-batching: A += (z/zdA)*sA, W += (z%zmB)*sB, C += z*sC.
__global__ void __launch_bounds__(256) sgemm_bias(
    const float* __restrict__ A, const float* __restrict__ W,
    const float* __restrict__ bias, float* __restrict__ C,
    int M, int N, int K,
    int zdA, long long sA, int zmB, long long sB, long long sC)
{
    __shared__ __align__(16) float As[16][128];
    __shared__ __align__(16) float Bs[16][128];

    const int z = blockIdx.z;
    A += (long long)(z / zdA) * sA;
    W += (long long)(z % zmB) * sB;
    C += (long long)z * sC;

    const int tid = threadIdx.x;
    const int m0 = blockIdx.y * 128;
    const int n0 = blockIdx.x * 128;
    const int tm = tid >> 4;   // 0..15
    const int tn = tid & 15;   // 0..15

    float acc[8][8];
#pragma unroll
    for (int i = 0; i < 8; i++)
#pragma unroll
        for (int j = 0; j < 8; j++) acc[i][j] = 0.f;

    for (int k0 = 0; k0 < K; k0 += 16) {
#pragma unroll
        for (int it = 0; it < 2; it++) {
            int idx = tid + it * 256;        // 0..511
            int r = idx >> 2;                // 0..127
            int c = (idx & 3) << 2;          // 0,4,8,12
            float4 v = *reinterpret_cast<const float4*>(A + (size_t)(m0 + r) * K + k0 + c);
            As[c + 0][r] = v.x; As[c + 1][r] = v.y; As[c + 2][r] = v.z; As[c + 3][r] = v.w;
        }
#pragma unroll
        for (int it = 0; it < 2; it++) {
            int idx = tid + it * 256;
            int r = idx >> 2;
            int c = (idx & 3) << 2;
            int n = n0 + r;
            float4 v = make_float4(0.f, 0.f, 0.f, 0.f);
            if (n < N) v = *reinterpret_cast<const float4*>(W + (size_t)n * K + k0 + c);
            Bs[c + 0][r] = v.x; Bs[c + 1][r] = v.y; Bs[c + 2][r] = v.z; Bs[c + 3][r] = v.w;
        }
        __syncthreads();

#pragma unroll
        for (int kk = 0; kk < 16; kk++) {
            float4 a0 = *reinterpret_cast<const float4*>(&As[kk][tm * 4]);
            float4 a1 = *reinterpret_cast<const float4*>(&As[kk][tm * 4 + 64]);
            float4 b0 = *reinterpret_cast<const float4*>(&Bs[kk][tn * 4]);
            float4 b1 = *reinterpret_cast<const float4*>(&Bs[kk][tn * 4 + 64]);
            float a[8] = {a0.x, a0.y, a0.z, a0.w, a1.x, a1.y, a1.z, a1.w};
            float b[8] = {b0.x, b0.y, b0.z, b0.w, b1.x, b1.y, b1.z, b1.w};
#pragma unroll
            for (int i = 0; i < 8; i++)
#pragma unroll
                for (int j = 0; j < 8; j++) acc[i][j] = fmaf(a[i], b[j], acc[i][j]);
        }
        __syncthreads();
    }

#pragma unroll
    for (int i = 0; i < 8; i++) {
        int m = m0 + tm * 4 + (i & 3) + ((i >> 2) << 6);
        float* crow = C + (size_t)m * N;
#pragma unroll
        for (int jj = 0; jj < 2; jj++) {
            int n = n0 + tn * 4 + (jj << 6);
            if (n < N) {   // N is always a multiple of 4 -> whole float4 in range
                float4 bv = make_float4(0.f, 0.f, 0.f, 0.f);
                if (bias) bv = *reinterpret_cast<const float4*>(bias + n);
                float4 v;
                v.x = acc[i][jj * 4 + 0] + bv.x;
                v.y = acc[i][jj * 4 + 1] + bv.y;
                v.z = acc[i][jj * 4 + 2] + bv.z;
                v.w = acc[i][jj * 4 + 3] + bv.w;
                *reinterpret_cast<float4*>(crow + n) = v;
            }
        }
    }
}

// ---------------- RMSNorm (in-place), one block per row --------------------
__global__ void __launch_bounds__(256) rmsnorm_k(float* __restrict__ x,
                                                 const float* __restrict__ w, int D)
{
    const int row = blockIdx.x;
    float* xr = x + (size_t)row * D;
    float ss = 0.f;
    for (int i = threadIdx.x; i < D; i += 256) { float v = xr[i]; ss = fmaf(v, v, ss); }
    __shared__ float red[8];
#pragma unroll
    for (int d = 16; d; d >>= 1) ss += __shfl_xor_sync(0xffffffffu, ss, d);
    if ((threadIdx.x & 31) == 0) red[threadIdx.x >> 5] = ss;
    __syncthreads();
    if (threadIdx.x == 0) {
        float t = 0.f;
#pragma unroll
        for (int i = 0; i < 8; i++) t += red[i];
        red[0] = t;
    }
    __syncthreads();
    const float r = rsqrtf(red[0] / (float)D + 1e-6f);
    for (int i = threadIdx.x; i < D; i += 256) xr[i] = w[i] * (xr[i] * r);
}

// ---------------- RoPE tables (fp64 trig: cosf range reduction at ~2047 rad is unsafe) ----
__global__ void rope_tab_k(float* __restrict__ ct, float* __restrict__ st)
{
    const int pos = blockIdx.x;          // 0..2047
    const int j = threadIdx.x;           // 0..31
    double inv = pow(10000.0, -((double)j) / 32.0);
    float ang = (float)pos * (float)inv; // match numpy float32 t*inv_freq
    float c = (float)cos((double)ang);
    float s = (float)sin((double)ang);
    ct[pos * 64 + j] = c; ct[pos * 64 + j + 32] = c;
    st[pos * 64 + j] = s; st[pos * 64 + j + 32] = s;
}

// ---------------- kv split: rmsnorm first 512, rope last 64 -----------------
__global__ void __launch_bounds__(256) kvprep_k(
    const float* __restrict__ kvf, const float* __restrict__ w,
    float* __restrict__ kvn, float* __restrict__ kpe,
    const float* __restrict__ ct, const float* __restrict__ st)
{
    const int row = blockIdx.x;
    const float* xr = kvf + (size_t)row * 576;
    float ss = 0.f;
    for (int i = threadIdx.x; i < 512; i += 256) { float v = xr[i]; ss = fmaf(v, v, ss); }
    __shared__ float red[8];
#pragma unroll
    for (int d = 16; d; d >>= 1) ss += __shfl_xor_sync(0xffffffffu, ss, d);
    if ((threadIdx.x & 31) == 0) red[threadIdx.x >> 5] = ss;
    __syncthreads();
    if (threadIdx.x == 0) {
        float t = 0.f;
#pragma unroll
        for (int i = 0; i < 8; i++) t += red[i];
        red[0] = t;
    }
    __syncthreads();
    const float r = rsqrtf(red[0] / 512.f + 1e-6f);
    for (int i = threadIdx.x; i < 512; i += 256)
        kvn[(size_t)row * 512 + i] = w[i] * (xr[i] * r);

    if (threadIdx.x < 32) {
        const int j = threadIdx.x;
        const int pos = row & (S_ - 1);
        float c = ct[pos * 64 + j], s = st[pos * 64 + j];
        float x1 = xr[512 + j], x2 = xr[544 + j];
        kpe[(size_t)row * 64 + j]      = x1 * c - x2 * s;
        kpe[(size_t)row * 64 + 32 + j] = x2 * c + x1 * s;
    }
}

// ---------------- rope on q_pe slice of each head (in-place) ----------------
__global__ void __launch_bounds__(256) ropeq_k(float* __restrict__ q,
                                               const float* __restrict__ ct,
                                               const float* __restrict__ st)
{
    const int idx = blockIdx.x * 256 + threadIdx.x;  // < 4096*16*32
    const int row = idx >> 9;
    const int h = (idx >> 5) & 15;
    const int j = idx & 31;
    const int pos = row & (S_ - 1);
    float* p = q + (size_t)row * 3072 + h * 192 + 128;
    float c = ct[pos * 64 + j], s = st[pos * 64 + j];
    float x1 = p[j], x2 = p[j + 32];
    p[j]      = x1 * c - x2 * s;
    p[j + 32] = x2 * c + x1 * s;
}

// ---------------- flash attention (absorbed MLA): qk-dim 192, v-dim 128 -----
// grid (32, 16, 2) = (S/64, NH, B); 256 threads; online softmax; O in regs.
__global__ void __launch_bounds__(256) attn_k(
    const float* __restrict__ Q,    // [4096, 3072]
    const float* __restrict__ KV,   // [32][2048][256]: k_abs | v_abs
    const float* __restrict__ Kpe,  // [4096, 64]
    const int*   __restrict__ msk,  // [2, 2048]
    float* __restrict__ Out)        // [4096, 2048]
{
    const int qb = blockIdx.x, h = blockIdx.y, b = blockIdx.z;
    const int tid = threadIdx.x;
    extern __shared__ float sm[];
    float* sQT  = sm;                 // [192][68] transposed
    float* sKT  = sQT + 192 * 68;     // [128][68] transposed
    float* sKpT = sKT + 128 * 68;     // [64][68]  transposed
    float* sV   = sKpT + 64 * 68;     // [64][132] row-major
    float* sP   = sV + 64 * 132;      // [64][68]

    const int s0 = qb * 64;
    const float* Qb = Q + (size_t)(b * 2048 + s0) * 3072 + h * 192;
    for (int idx = tid; idx < 64 * 48; idx += 256) {
        int r = idx / 48, c4 = idx % 48;
        float4 v = *reinterpret_cast<const float4*>(Qb + (size_t)r * 3072 + c4 * 4);
        int c = c4 * 4;
        sQT[(c + 0) * 68 + r] = v.x; sQT[(c + 1) * 68 + r] = v.y;
        sQT[(c + 2) * 68 + r] = v.z; sQT[(c + 3) * 68 + r] = v.w;
    }

    const int rg = tid >> 4, cg = tid & 15;
    const int r0 = rg * 4;
    const float scale = 0.07216878364870322f;  // 1/sqrt(192)

    float m_i[4], l_i[4], o[4][8];
#pragma unroll
    for (int i = 0; i < 4; i++) {
        m_i[i] = -3.0e38f; l_i[i] = 0.f;
#pragma unroll
        for (int j = 0; j < 8; j++) o[i][j] = 0.f;
    }

    const int* mrow = msk + (size_t)b * 2048;

    for (int kt = 0; kt <= qb; kt++) {
        __syncthreads();  // previous iteration's sP/sV reads done
        const float* KVb = KV + ((size_t)(b * 16 + h) * 2048 + kt * 64) * 256;
        for (int idx = tid; idx < 64 * 64; idx += 256) {
            int r = idx >> 6, c4 = idx & 63;
            float4 v = *reinterpret_cast<const float4*>(KVb + (size_t)r * 256 + c4 * 4);
            if (c4 < 32) {
                int c = c4 * 4;
                sKT[(c + 0) * 68 + r] = v.x; sKT[(c + 1) * 68 + r] = v.y;
                sKT[(c + 2) * 68 + r] = v.z; sKT[(c + 3) * 68 + r] = v.w;
            } else {
                *reinterpret_cast<float4*>(sV + (size_t)r * 132 + (c4 - 32) * 4) = v;
            }
        }
        const float* Kpb = Kpe + (size_t)(b * 2048 + kt * 64) * 64;
        for (int idx = tid; idx < 64 * 16; idx += 256) {
            int r = idx >> 4, c4 = idx & 15;
            float4 v = *reinterpret_cast<const float4*>(Kpb + (size_t)r * 64 + c4 * 4);
            int c = c4 * 4;
            sKpT[(c + 0) * 68 + r] = v.x; sKpT[(c + 1) * 68 + r] = v.y;
            sKpT[(c + 2) * 68 + r] = v.z; sKpT[(c + 3) * 68 + r] = v.w;
        }
        __syncthreads();

        float sc[4][4];
#pragma unroll
        for (int i = 0; i < 4; i++)
#pragma unroll
            for (int j = 0; j < 4; j++) sc[i][j] = 0.f;

#pragma unroll 4
        for (int kk = 0; kk < 128; kk++) {
            float4 a  = *reinterpret_cast<const float4*>(sQT + kk * 68 + r0);
            float4 bb = *reinterpret_cast<const float4*>(sKT + kk * 68 + cg * 4);
            float av[4] = {a.x, a.y, a.z, a.w}, bv[4] = {bb.x, bb.y, bb.z, bb.w};
#pragma unroll
            for (int i = 0; i < 4; i++)
#pragma unroll
                for (int j = 0; j < 4; j++) sc[i][j] = fmaf(av[i], bv[j], sc[i][j]);
        }
#pragma unroll 4
        for (int kk = 0; kk < 64; kk++) {
            float4 a  = *reinterpret_cast<const float4*>(sQT + (128 + kk) * 68 + r0);
            float4 bb = *reinterpret_cast<const float4*>(sKpT + kk * 68 + cg * 4);
            float av[4] = {a.x, a.y, a.z, a.w}, bv[4] = {bb.x, bb.y, bb.z, bb.w};
#pragma unroll
            for (int i = 0; i < 4; i++)
#pragma unroll
                for (int j = 0; j < 4; j++) sc[i][j] = fmaf(av[i], bv[j], sc[i][j]);
        }

        // scale + mask (causal only needed on the diagonal tile)
        const bool diag = (kt == qb);
        int mv[4];
#pragma unroll
        for (int j = 0; j < 4; j++) mv[j] = mrow[kt * 64 + cg * 4 + j];
#pragma unroll
        for (int i = 0; i < 4; i++) {
            int sg = s0 + r0 + i;
#pragma unroll
            for (int j = 0; j < 4; j++) {
                int t = kt * 64 + cg * 4 + j;
                float v = sc[i][j] * scale;
                if ((diag && t > sg) || mv[j] == 0) v = -1e15f;
                sc[i][j] = v;
            }
        }

        // online softmax
        float alpha[4];
#pragma unroll
        for (int i = 0; i < 4; i++) {
            float tmax = fmaxf(fmaxf(sc[i][0], sc[i][1]), fmaxf(sc[i][2], sc[i][3]));
#pragma unroll
            for (int d = 1; d < 16; d <<= 1) tmax = fmaxf(tmax, __shfl_xor_sync(0xffffffffu, tmax, d));
            float nm = fmaxf(m_i[i], tmax);
            float rs = 0.f;
#pragma unroll
            for (int j = 0; j < 4; j++) { float p = expf(sc[i][j] - nm); sc[i][j] = p; rs += p; }
#pragma unroll
            for (int d = 1; d < 16; d <<= 1) rs += __shfl_xor_sync(0xffffffffu, rs, d);
            alpha[i] = expf(m_i[i] - nm);
            l_i[i] = l_i[i] * alpha[i] + rs;
            m_i[i] = nm;
            *reinterpret_cast<float4*>(sP + (r0 + i) * 68 + cg * 4) =
                make_float4(sc[i][0], sc[i][1], sc[i][2], sc[i][3]);
        }
        __syncthreads();

        // rescale O, then O += P @ V
#pragma unroll
        for (int i = 0; i < 4; i++)
#pragma unroll
            for (int j = 0; j < 8; j++) o[i][j] *= alpha[i];
#pragma unroll 2
        for (int kk = 0; kk < 64; kk++) {
            float pv[4];
#pragma unroll
            for (int i = 0; i < 4; i++) pv[i] = sP[(r0 + i) * 68 + kk];
            float4 v0 = *reinterpret_cast<const float4*>(sV + kk * 132 + cg * 4);
            float4 v1 = *reinterpret_cast<const float4*>(sV + kk * 132 + cg * 4 + 64);
            float vv[8] = {v0.x, v0.y, v0.z, v0.w, v1.x, v1.y, v1.z, v1.w};
#pragma unroll
            for (int i = 0; i < 4; i++)
#pragma unroll
                for (int j = 0; j < 8; j++) o[i][j] = fmaf(pv[i], vv[j], o[i][j]);
        }
    }

#pragma unroll
    for (int i = 0; i < 4; i++) {
        float inv = 1.f / l_i[i];
        float* orow = Out + (size_t)(b * 2048 + s0 + r0 + i) * 2048 + h * 128;
        *reinterpret_cast<float4*>(orow + cg * 4) =
            make_float4(o[i][0] * inv, o[i][1] * inv, o[i][2] * inv, o[i][3] * inv);
        *reinterpret_cast<float4*>(orow + cg * 4 + 64) =
            make_float4(o[i][4] * inv, o[i][5] * inv, o[i][6] * inv, o[i][7] * inv);
    }
}

// ------------------------------- host side ---------------------------------
extern "C" void kernel_launch(void* const* d_in, const int* in_sizes, int n_in,
                              void* d_out, int out_size)
{
    (void)in_sizes; (void)n_in; (void)out_size;
    const float* x        = (const float*)d_in[0];
    const int*   mask     = (const int*)  d_in[1];
    const float* wq_a_w   = (const float*)d_in[2];
    const float* wq_a_b   = (const float*)d_in[3];
    const float* q_norm_w = (const float*)d_in[4];
    const float* wq_b_w   = (const float*)d_in[5];
    const float* wq_b_b   = (const float*)d_in[6];
    const float* wkv_a_w  = (const float*)d_in[7];
    const float* wkv_a_b  = (const float*)d_in[8];
    const float* kv_norm_w= (const float*)d_in[9];
    const float* wkv_b_w  = (const float*)d_in[10];
    const float* wo_w     = (const float*)d_in[11];
    const float* wo_b     = (const float*)d_in[12];
    float* out = (float*)d_out;

    float *qa, *q, *kvf, *kvn, *kpe, *kvab, *att, *ct, *st;
    cudaGetSymbolAddress((void**)&qa,   g_qa);
    cudaGetSymbolAddress((void**)&q,    g_q);
    cudaGetSymbolAddress((void**)&kvf,  g_kvf);
    cudaGetSymbolAddress((void**)&kvn,  g_kvn);
    cudaGetSymbolAddress((void**)&kpe,  g_kpe);
    cudaGetSymbolAddress((void**)&kvab, g_kvab);
    cudaGetSymbolAddress((void**)&att,  g_att);
    cudaGetSymbolAddress((void**)&ct,   g_cos);
    cudaGetSymbolAddress((void**)&st,   g_sin);

    rope_tab_k<<<S_, 32>>>(ct, st);

    // q_a = x @ wq_a^T + b   [4096,2048]x[1536,2048]
    { dim3 g(QL_ / 128, ROWS_ / 128, 1);
      sgemm_bias<<<g, 256>>>(x, wq_a_w, wq_a_b, qa, ROWS_, QL_, H_, 1, 0, 1, 0, 0); }
    rmsnorm_k<<<ROWS_, 256>>>(qa, q_norm_w, QL_);
    // q = q_a @ wq_b^T + b   [4096,1536]x[3072,1536]
    { dim3 g((NH_ * QKH_) / 128, ROWS_ / 128, 1);
      sgemm_bias<<<g, 256>>>(qa, wq_b_w, wq_b_b, q, ROWS_, NH_ * QKH_, QL_, 1, 0, 1, 0, 0); }
    // kv_full = x @ wkv_a^T + b   [4096,2048]x[576,2048]
    { dim3 g((KVL_ + ROPE_ + 127) / 128, ROWS_ / 128, 1);
      sgemm_bias<<<g, 256>>>(x, wkv_a_w, wkv_a_b, kvf, ROWS_, KVL_ + ROPE_, H_, 1, 0, 1, 0, 0); }
    kvprep_k<<<ROWS_, 256>>>(kvf, kv_norm_w, kvn, kpe, ct, st);
    ropeq_k<<<(ROWS_ * NH_ * 32) / 256, 256>>>(q, ct, st);

    // absorbed K/V: per (b,h): kvab[z] = kvn[b] (2048x512) @ wkv_b[h] (256x512)^T
    { dim3 g(256 / 128, S_ / 128, B_ * NH_);
      sgemm_bias<<<g, 256>>>(kvn, wkv_b_w, nullptr, kvab, S_, 256, KVL_,
                             NH_, (long long)S_ * KVL_,
                             NH_, 256LL * KVL_,
                             (long long)S_ * 256); }

    // flash attention
    const int smem = (192 * 68 + 128 * 68 + 64 * 68 + 64 * 132 + 64 * 68) * 4;  // ~152KB
    cudaFuncSetAttribute(attn_k, cudaFuncAttributeMaxDynamicSharedMemorySize, smem);
    attn_k<<<dim3(S_ / 64, NH_, B_), 256, smem>>>(q, kvab, kpe, mask, att);

    // out = att @ wo^T + b   [4096,2048]x[2048,2048]
    { dim3 g(H_ / 128, ROWS_ / 128, 1);
      sgemm_bias<<<g, 256>>>(att, wo_w, wo_b, out, ROWS_, H_, NH_ * VD_, 1, 0, 1, 0, 0); }
}

// round 8
// speedup vs baseline: 1.6854x; 1.6854x over previous
#include <cuda_runtime.h>
#include <math.h>
#include <stddef.h>
#include <stdint.h>

// MLA shapes (compile-time constants)
#define B_    2
#define S_    2048
#define H_    2048
#define NH_   16
#define QL_   1536
#define KVL_  512
#define NOPE_ 128
#define ROPE_ 64
#define VD_   128
#define QKH_  192
#define ROWS_ (B_*S_)   // 4096

// ---------------- scratch (device globals: no allocs allowed) ----------------
__device__ float g_qa  [(size_t)ROWS_*QL_];
__device__ float g_q   [(size_t)ROWS_*NH_*QKH_];
__device__ float g_kvf [(size_t)ROWS_*(KVL_+ROPE_)];
__device__ float g_kvn [(size_t)ROWS_*KVL_];
__device__ float g_kpe [(size_t)ROWS_*ROPE_];
__device__ float g_kvab[(size_t)B_*NH_*S_*256];
__device__ float g_att [(size_t)ROWS_*NH_*VD_];
__device__ float g_cos [(size_t)S_*ROPE_];
__device__ float g_sin [(size_t)S_*ROPE_];

// ---------------- tf32 helpers ----------------
__device__ __forceinline__ uint32_t f2tf(float x) {
    uint32_t r;
    asm("cvt.rna.tf32.f32 %0, %1;" : "=r"(r) : "f"(x));
    return r;
}

// ---------------- tensor-core GEMM: C = A(MxK) @ W(NxK)^T + bias ------------
// tf32 mma.sync m16n8k8, fp32 accumulate. 128x128 block tile, BK=32,
// 256 threads = 8 warps in 2x4 (warp tile 64x32 -> 4x4 m16n8 tiles).
// z-batching: A += (z/zdA)*sA, W += (z%zmB)*sB, C += z*sC.
// Requires: M % 128 == 0, K % 32 == 0, N % 8 == 0 (N<128 handled by guards).
__global__ void __launch_bounds__(256) sgemm_bias(
    const float* __restrict__ A, const float* __restrict__ W,
    const float* __restrict__ bias, float* __restrict__ C,
    int M, int N, int K,
    int zdA, long long sA, int zmB, long long sB, long long sC)
{
    __shared__ __align__(16) uint32_t As[128][36];   // [row][k], pad 36 -> conflict-free frags
    __shared__ __align__(16) uint32_t Bs[128][36];   // [n][k]

    const int z = blockIdx.z;
    A += (long long)(z / zdA) * sA;
    W += (long long)(z % zmB) * sB;
    C += (long long)z * sC;

    const int tid  = threadIdx.x;
    const int warp = tid >> 5, lane = tid & 31;
    const int wm = warp >> 2;        // 0..1 : row block of 64
    const int wn = warp & 3;         // 0..3 : col block of 32
    const int g  = lane >> 2;        // groupID 0..7
    const int tg = lane & 3;         // thread-in-group 0..3
    const int m0 = blockIdx.y * 128;
    const int n0 = blockIdx.x * 128;

    float acc[4][4][4];
#pragma unroll
    for (int mt = 0; mt < 4; mt++)
#pragma unroll
        for (int nt = 0; nt < 4; nt++)
#pragma unroll
            for (int r = 0; r < 4; r++) acc[mt][nt][r] = 0.f;

    for (int k0 = 0; k0 < K; k0 += 32) {
        // stage A tile (128x32) -> tf32 in smem
#pragma unroll
        for (int it = 0; it < 4; it++) {
            int idx = tid + it * 256;          // 0..1023 float4 slots
            int r = idx >> 3;
            int c = (idx & 7) << 2;
            float4 v = *reinterpret_cast<const float4*>(A + (size_t)(m0 + r) * K + k0 + c);
            As[r][c + 0] = f2tf(v.x); As[r][c + 1] = f2tf(v.y);
            As[r][c + 2] = f2tf(v.z); As[r][c + 3] = f2tf(v.w);
        }
        // stage B tile (128x32), rows are output cols (W row-major [N][K])
#pragma unroll
        for (int it = 0; it < 4; it++) {
            int idx = tid + it * 256;
            int r = idx >> 3;
            int c = (idx & 7) << 2;
            int n = n0 + r;
            float4 v = make_float4(0.f, 0.f, 0.f, 0.f);
            if (n < N) v = *reinterpret_cast<const float4*>(W + (size_t)n * K + k0 + c);
            Bs[r][c + 0] = f2tf(v.x); Bs[r][c + 1] = f2tf(v.y);
            Bs[r][c + 2] = f2tf(v.z); Bs[r][c + 3] = f2tf(v.w);
        }
        __syncthreads();

#pragma unroll
        for (int ks = 0; ks < 4; ks++) {
            const int kc = ks * 8 + tg;
            uint32_t af[4][4], bf[4][2];
#pragma unroll
            for (int mt = 0; mt < 4; mt++) {
                int rb = wm * 64 + mt * 16 + g;
                af[mt][0] = As[rb][kc];       af[mt][1] = As[rb + 8][kc];
                af[mt][2] = As[rb][kc + 4];   af[mt][3] = As[rb + 8][kc + 4];
            }
#pragma unroll
            for (int nt = 0; nt < 4; nt++) {
                int nb = wn * 32 + nt * 8 + g;
                bf[nt][0] = Bs[nb][kc];       bf[nt][1] = Bs[nb][kc + 4];
            }
#pragma unroll
            for (int mt = 0; mt < 4; mt++)
#pragma unroll
                for (int nt = 0; nt < 4; nt++) {
                    asm volatile(
                        "mma.sync.aligned.m16n8k8.row.col.f32.tf32.tf32.f32 "
                        "{%0,%1,%2,%3}, {%4,%5,%6,%7}, {%8,%9}, {%0,%1,%2,%3};"
                        : "+f"(acc[mt][nt][0]), "+f"(acc[mt][nt][1]),
                          "+f"(acc[mt][nt][2]), "+f"(acc[mt][nt][3])
                        : "r"(af[mt][0]), "r"(af[mt][1]), "r"(af[mt][2]), "r"(af[mt][3]),
                          "r"(bf[nt][0]), "r"(bf[nt][1]));
                }
        }
        __syncthreads();
    }

    // epilogue: c0 (g, 2tg) c1 (g, 2tg+1) c2 (g+8, 2tg) c3 (g+8, 2tg+1)
#pragma unroll
    for (int mt = 0; mt < 4; mt++) {
        int row = m0 + wm * 64 + mt * 16 + g;
#pragma unroll
        for (int nt = 0; nt < 4; nt++) {
            int col = n0 + wn * 32 + nt * 8 + (tg << 1);
            if (col < N) {
                float2 bv = make_float2(0.f, 0.f);
                if (bias) bv = *reinterpret_cast<const float2*>(bias + col);
                float2 v0 = make_float2(acc[mt][nt][0] + bv.x, acc[mt][nt][1] + bv.y);
                float2 v1 = make_float2(acc[mt][nt][2] + bv.x, acc[mt][nt][3] + bv.y);
                *reinterpret_cast<float2*>(C + (size_t)row * N + col) = v0;
                *reinterpret_cast<float2*>(C + (size_t)(row + 8) * N + col) = v1;
            }
        }
    }
}

// ---------------- RMSNorm (in-place), one block per row --------------------
__global__ void __launch_bounds__(256) rmsnorm_k(float* __restrict__ x,
                                                 const float* __restrict__ w, int D)
{
    const int row = blockIdx.x;
    float* xr = x + (size_t)row * D;
    float ss = 0.f;
    for (int i = threadIdx.x; i < D; i += 256) { float v = xr[i]; ss = fmaf(v, v, ss); }
    __shared__ float red[8];
#pragma unroll
    for (int d = 16; d; d >>= 1) ss += __shfl_xor_sync(0xffffffffu, ss, d);
    if ((threadIdx.x & 31) == 0) red[threadIdx.x >> 5] = ss;
    __syncthreads();
    if (threadIdx.x == 0) {
        float t = 0.f;
#pragma unroll
        for (int i = 0; i < 8; i++) t += red[i];
        red[0] = t;
    }
    __syncthreads();
    const float r = rsqrtf(red[0] / (float)D + 1e-6f);
    for (int i = threadIdx.x; i < D; i += 256) xr[i] = w[i] * (xr[i] * r);
}

// ---------------- RoPE tables (fp64 trig for range safety) ------------------
__global__ void rope_tab_k(float* __restrict__ ct, float* __restrict__ st)
{
    const int pos = blockIdx.x;
    const int j = threadIdx.x;
    double inv = pow(10000.0, -((double)j) / 32.0);
    float ang = (float)pos * (float)inv;
    float c = (float)cos((double)ang);
    float s = (float)sin((double)ang);
    ct[pos * 64 + j] = c; ct[pos * 64 + j + 32] = c;
    st[pos * 64 + j] = s; st[pos * 64 + j + 32] = s;
}

// ---------------- kv split: rmsnorm first 512, rope last 64 -----------------
__global__ void __launch_bounds__(256) kvprep_k(
    const float* __restrict__ kvf, const float* __restrict__ w,
    float* __restrict__ kvn, float* __restrict__ kpe,
    const float* __restrict__ ct, const float* __restrict__ st)
{
    const int row = blockIdx.x;
    const float* xr = kvf + (size_t)row * 576;
    float ss = 0.f;
    for (int i = threadIdx.x; i < 512; i += 256) { float v = xr[i]; ss = fmaf(v, v, ss); }
    __shared__ float red[8];
#pragma unroll
    for (int d = 16; d; d >>= 1) ss += __shfl_xor_sync(0xffffffffu, ss, d);
    if ((threadIdx.x & 31) == 0) red[threadIdx.x >> 5] = ss;
    __syncthreads();
    if (threadIdx.x == 0) {
        float t = 0.f;
#pragma unroll
        for (int i = 0; i < 8; i++) t += red[i];
        red[0] = t;
    }
    __syncthreads();
    const float r = rsqrtf(red[0] / 512.f + 1e-6f);
    for (int i = threadIdx.x; i < 512; i += 256)
        kvn[(size_t)row * 512 + i] = w[i] * (xr[i] * r);

    if (threadIdx.x < 32) {
        const int j = threadIdx.x;
        const int pos = row & (S_ - 1);
        float c = ct[pos * 64 + j], s = st[pos * 64 + j];
        float x1 = xr[512 + j], x2 = xr[544 + j];
        kpe[(size_t)row * 64 + j]      = x1 * c - x2 * s;
        kpe[(size_t)row * 64 + 32 + j] = x2 * c + x1 * s;
    }
}

// ---------------- rope on q_pe slice of each head (in-place) ----------------
__global__ void __launch_bounds__(256) ropeq_k(float* __restrict__ q,
                                               const float* __restrict__ ct,
                                               const float* __restrict__ st)
{
    const int idx = blockIdx.x * 256 + threadIdx.x;
    const int row = idx >> 9;
    const int h = (idx >> 5) & 15;
    const int j = idx & 31;
    const int pos = row & (S_ - 1);
    float* p = q + (size_t)row * 3072 + h * 192 + 128;
    float c = ct[pos * 64 + j], s = st[pos * 64 + j];
    float x1 = p[j], x2 = p[j + 32];
    p[j]      = x1 * c - x2 * s;
    p[j + 32] = x2 * c + x1 * s;
}

// ---------------- flash attention (absorbed MLA): qk-dim 192, v-dim 128 -----
__global__ void __launch_bounds__(256) attn_k(
    const float* __restrict__ Q,
    const float* __restrict__ KV,
    const float* __restrict__ Kpe,
    const int*   __restrict__ msk,
    float* __restrict__ Out)
{
    const int qb = blockIdx.x, h = blockIdx.y, b = blockIdx.z;
    const int tid = threadIdx.x;
    extern __shared__ float sm[];
    float* sQT  = sm;
    float* sKT  = sQT + 192 * 68;
    float* sKpT = sKT + 128 * 68;
    float* sV   = sKpT + 64 * 68;
    float* sP   = sV + 64 * 132;

    const int s0 = qb * 64;
    const float* Qb = Q + (size_t)(b * 2048 + s0) * 3072 + h * 192;
    for (int idx = tid; idx < 64 * 48; idx += 256) {
        int r = idx / 48, c4 = idx % 48;
        float4 v = *reinterpret_cast<const float4*>(Qb + (size_t)r * 3072 + c4 * 4);
        int c = c4 * 4;
        sQT[(c + 0) * 68 + r] = v.x; sQT[(c + 1) * 68 + r] = v.y;
        sQT[(c + 2) * 68 + r] = v.z; sQT[(c + 3) * 68 + r] = v.w;
    }

    const int rg = tid >> 4, cg = tid & 15;
    const int r0 = rg * 4;
    const float scale = 0.07216878364870322f;

    float m_i[4], l_i[4], o[4][8];
#pragma unroll
    for (int i = 0; i < 4; i++) {
        m_i[i] = -3.0e38f; l_i[i] = 0.f;
#pragma unroll
        for (int j = 0; j < 8; j++) o[i][j] = 0.f;
    }

    const int* mrow = msk + (size_t)b * 2048;

    for (int kt = 0; kt <= qb; kt++) {
        __syncthreads();
        const float* KVb = KV + ((size_t)(b * 16 + h) * 2048 + kt * 64) * 256;
        for (int idx = tid; idx < 64 * 64; idx += 256) {
            int r = idx >> 6, c4 = idx & 63;
            float4 v = *reinterpret_cast<const float4*>(KVb + (size_t)r * 256 + c4 * 4);
            if (c4 < 32) {
                int c = c4 * 4;
                sKT[(c + 0) * 68 + r] = v.x; sKT[(c + 1) * 68 + r] = v.y;
                sKT[(c + 2) * 68 + r] = v.z; sKT[(c + 3) * 68 + r] = v.w;
            } else {
                *reinterpret_cast<float4*>(sV + (size_t)r * 132 + (c4 - 32) * 4) = v;
            }
        }
        const float* Kpb = Kpe + (size_t)(b * 2048 + kt * 64) * 64;
        for (int idx = tid; idx < 64 * 16; idx += 256) {
            int r = idx >> 4, c4 = idx & 15;
            float4 v = *reinterpret_cast<const float4*>(Kpb + (size_t)r * 64 + c4 * 4);
            int c = c4 * 4;
            sKpT[(c + 0) * 68 + r] = v.x; sKpT[(c + 1) * 68 + r] = v.y;
            sKpT[(c + 2) * 68 + r] = v.z; sKpT[(c + 3) * 68 + r] = v.w;
        }
        __syncthreads();

        float sc[4][4];
#pragma unroll
        for (int i = 0; i < 4; i++)
#pragma unroll
            for (int j = 0; j < 4; j++) sc[i][j] = 0.f;

#pragma unroll 4
        for (int kk = 0; kk < 128; kk++) {
            float4 a  = *reinterpret_cast<const float4*>(sQT + kk * 68 + r0);
            float4 bb = *reinterpret_cast<const float4*>(sKT + kk * 68 + cg * 4);
            float av[4] = {a.x, a.y, a.z, a.w}, bv[4] = {bb.x, bb.y, bb.z, bb.w};
#pragma unroll
            for (int i = 0; i < 4; i++)
#pragma unroll
                for (int j = 0; j < 4; j++) sc[i][j] = fmaf(av[i], bv[j], sc[i][j]);
        }
#pragma unroll 4
        for (int kk = 0; kk < 64; kk++) {
            float4 a  = *reinterpret_cast<const float4*>(sQT + (128 + kk) * 68 + r0);
            float4 bb = *reinterpret_cast<const float4*>(sKpT + kk * 68 + cg * 4);
            float av[4] = {a.x, a.y, a.z, a.w}, bv[4] = {bb.x, bb.y, bb.z, bb.w};
#pragma unroll
            for (int i = 0; i < 4; i++)
#pragma unroll
                for (int j = 0; j < 4; j++) sc[i][j] = fmaf(av[i], bv[j], sc[i][j]);
        }

        const bool diag = (kt == qb);
        int mv[4];
#pragma unroll
        for (int j = 0; j < 4; j++) mv[j] = mrow[kt * 64 + cg * 4 + j];
#pragma unroll
        for (int i = 0; i < 4; i++) {
            int sg = s0 + r0 + i;
#pragma unroll
            for (int j = 0; j < 4; j++) {
                int t = kt * 64 + cg * 4 + j;
                float v = sc[i][j] * scale;
                if ((diag && t > sg) || mv[j] == 0) v = -1e15f;
                sc[i][j] = v;
            }
        }

        float alpha[4];
#pragma unroll
        for (int i = 0; i < 4; i++) {
            float tmax = fmaxf(fmaxf(sc[i][0], sc[i][1]), fmaxf(sc[i][2], sc[i][3]));
#pragma unroll
            for (int d = 1; d < 16; d <<= 1) tmax = fmaxf(tmax, __shfl_xor_sync(0xffffffffu, tmax, d));
            float nm = fmaxf(m_i[i], tmax);
            float rs = 0.f;
#pragma unroll
            for (int j = 0; j < 4; j++) { float p = expf(sc[i][j] - nm); sc[i][j] = p; rs += p; }
#pragma unroll
            for (int d = 1; d < 16; d <<= 1) rs += __shfl_xor_sync(0xffffffffu, rs, d);
            alpha[i] = expf(m_i[i] - nm);
            l_i[i] = l_i[i] * alpha[i] + rs;
            m_i[i] = nm;
            *reinterpret_cast<float4*>(sP + (r0 + i) * 68 + cg * 4) =
                make_float4(sc[i][0], sc[i][1], sc[i][2], sc[i][3]);
        }
        __syncthreads();

#pragma unroll
        for (int i = 0; i < 4; i++)
#pragma unroll
            for (int j = 0; j < 8; j++) o[i][j] *= alpha[i];
#pragma unroll 2
        for (int kk = 0; kk < 64; kk++) {
            float pv[4];
#pragma unroll
            for (int i = 0; i < 4; i++) pv[i] = sP[(r0 + i) * 68 + kk];
            float4 v0 = *reinterpret_cast<const float4*>(sV + kk * 132 + cg * 4);
            float4 v1 = *reinterpret_cast<const float4*>(sV + kk * 132 + cg * 4 + 64);
            float vv[8] = {v0.x, v0.y, v0.z, v0.w, v1.x, v1.y, v1.z, v1.w};
#pragma unroll
            for (int i = 0; i < 4; i++)
#pragma unroll
                for (int j = 0; j < 8; j++) o[i][j] = fmaf(pv[i], vv[j], o[i][j]);
        }
    }

#pragma unroll
    for (int i = 0; i < 4; i++) {
        float inv = 1.f / l_i[i];
        float* orow = Out + (size_t)(b * 2048 + s0 + r0 + i) * 2048 + h * 128;
        *reinterpret_cast<float4*>(orow + cg * 4) =
            make_float4(o[i][0] * inv, o[i][1] * inv, o[i][2] * inv, o[i][3] * inv);
        *reinterpret_cast<float4*>(orow + cg * 4 + 64) =
            make_float4(o[i][4] * inv, o[i][5] * inv, o[i][6] * inv, o[i][7] * inv);
    }
}

// ------------------------------- host side ---------------------------------
extern "C" void kernel_launch(void* const* d_in, const int* in_sizes, int n_in,
                              void* d_out, int out_size)
{
    (void)in_sizes; (void)n_in; (void)out_size;
    const float* x        = (const float*)d_in[0];
    const int*   mask     = (const int*)  d_in[1];
    const float* wq_a_w   = (const float*)d_in[2];
    const float* wq_a_b   = (const float*)d_in[3];
    const float* q_norm_w = (const float*)d_in[4];
    const float* wq_b_w   = (const float*)d_in[5];
    const float* wq_b_b   = (const float*)d_in[6];
    const float* wkv_a_w  = (const float*)d_in[7];
    const float* wkv_a_b  = (const float*)d_in[8];
    const float* kv_norm_w= (const float*)d_in[9];
    const float* wkv_b_w  = (const float*)d_in[10];
    const float* wo_w     = (const float*)d_in[11];
    const float* wo_b     = (const float*)d_in[12];
    float* out = (float*)d_out;

    float *qa, *q, *kvf, *kvn, *kpe, *kvab, *att, *ct, *st;
    cudaGetSymbolAddress((void**)&qa,   g_qa);
    cudaGetSymbolAddress((void**)&q,    g_q);
    cudaGetSymbolAddress((void**)&kvf,  g_kvf);
    cudaGetSymbolAddress((void**)&kvn,  g_kvn);
    cudaGetSymbolAddress((void**)&kpe,  g_kpe);
    cudaGetSymbolAddress((void**)&kvab, g_kvab);
    cudaGetSymbolAddress((void**)&att,  g_att);
    cudaGetSymbolAddress((void**)&ct,   g_cos);
    cudaGetSymbolAddress((void**)&st,   g_sin);

    rope_tab_k<<<S_, 32>>>(ct, st);

    // q_a = x @ wq_a^T + b   [4096,2048]x[1536,2048]
    { dim3 g(QL_ / 128, ROWS_ / 128, 1);
      sgemm_bias<<<g, 256>>>(x, wq_a_w, wq_a_b, qa, ROWS_, QL_, H_, 1, 0, 1, 0, 0); }
    rmsnorm_k<<<ROWS_, 256>>>(qa, q_norm_w, QL_);
    // q = q_a @ wq_b^T + b   [4096,1536]x[3072,1536]
    { dim3 g((NH_ * QKH_) / 128, ROWS_ / 128, 1);
      sgemm_bias<<<g, 256>>>(qa, wq_b_w, wq_b_b, q, ROWS_, NH_ * QKH_, QL_, 1, 0, 1, 0, 0); }
    // kv_full = x @ wkv_a^T + b   [4096,2048]x[576,2048]
    { dim3 g((KVL_ + ROPE_ + 127) / 128, ROWS_ / 128, 1);
      sgemm_bias<<<g, 256>>>(x, wkv_a_w, wkv_a_b, kvf, ROWS_, KVL_ + ROPE_, H_, 1, 0, 1, 0, 0); }
    kvprep_k<<<ROWS_, 256>>>(kvf, kv_norm_w, kvn, kpe, ct, st);
    ropeq_k<<<(ROWS_ * NH_ * 32) / 256, 256>>>(q, ct, st);

    // absorbed K/V: per (b,h): kvab[z] = kvn[b] (2048x512) @ wkv_b[h] (256x512)^T
    { dim3 g(256 / 128, S_ / 128, B_ * NH_);
      sgemm_bias<<<g, 256>>>(kvn, wkv_b_w, nullptr, kvab, S_, 256, KVL_,
                             NH_, (long long)S_ * KVL_,
                             NH_, 256LL * KVL_,
                             (long long)S_ * 256); }

    // flash attention
    const int smem = (192 * 68 + 128 * 68 + 64 * 68 + 64 * 132 + 64 * 68) * 4;
    cudaFuncSetAttribute(attn_k, cudaFuncAttributeMaxDynamicSharedMemorySize, smem);
    attn_k<<<dim3(S_ / 64, NH_, B_), 256, smem>>>(q, kvab, kpe, mask, att);

    // out = att @ wo^T + b   [4096,2048]x[2048,2048]
    { dim3 g(H_ / 128, ROWS_ / 128, 1);
      sgemm_bias<<<g, 256>>>(att, wo_w, wo_b, out, ROWS_, H_, NH_ * VD_, 1, 0, 1, 0, 0); }
}

// round 9
// speedup vs baseline: 2.0378x; 1.2091x over previous
#include <cuda_runtime.h>
#include <math.h>
#include <stddef.h>
#include <stdint.h>

// MLA shapes (compile-time constants)
#define B_    2
#define S_    2048
#define H_    2048
#define NH_   16
#define QL_   1536
#define KVL_  512
#define NOPE_ 128
#define ROPE_ 64
#define VD_   128
#define QKH_  192
#define ROWS_ (B_*S_)   // 4096

// ---------------- scratch (device globals: no allocs allowed) ----------------
__device__ float g_qa  [(size_t)ROWS_*QL_];
__device__ float g_q   [(size_t)ROWS_*NH_*QKH_];
__device__ float g_kvf [(size_t)ROWS_*(KVL_+ROPE_)];
__device__ float g_kvn [(size_t)ROWS_*KVL_];
__device__ float g_kpe [(size_t)ROWS_*ROPE_];
__device__ float g_kvab[(size_t)B_*NH_*S_*256];
__device__ float g_att [(size_t)ROWS_*NH_*VD_];
__device__ float g_cos [(size_t)S_*ROPE_];
__device__ float g_sin [(size_t)S_*ROPE_];

// ---------------- tf32 helpers ----------------
__device__ __forceinline__ uint32_t f2tf(float x) {
    uint32_t r;
    asm("cvt.rna.tf32.f32 %0, %1;" : "=r"(r) : "f"(x));
    return r;
}

#define MMA_TF32(d, a0, a1, a2, a3, b0, b1)                                  \
    asm volatile(                                                            \
        "mma.sync.aligned.m16n8k8.row.col.f32.tf32.tf32.f32 "                \
        "{%0,%1,%2,%3}, {%4,%5,%6,%7}, {%8,%9}, {%0,%1,%2,%3};"              \
        : "+f"((d)[0]), "+f"((d)[1]), "+f"((d)[2]), "+f"((d)[3])             \
        : "r"(a0), "r"(a1), "r"(a2), "r"(a3), "r"(b0), "r"(b1))

// ---------------- tensor-core GEMM: C = A(MxK) @ W(NxK)^T + bias ------------
// tf32 mma.sync m16n8k8, fp32 accumulate. 128x128 block tile, BK=32,
// 256 threads = 8 warps in 2x4 (warp tile 64x32 -> 4x4 m16n8 tiles).
__global__ void __launch_bounds__(256) sgemm_bias(
    const float* __restrict__ A, const float* __restrict__ W,
    const float* __restrict__ bias, float* __restrict__ C,
    int M, int N, int K,
    int zdA, long long sA, int zmB, long long sB, long long sC)
{
    __shared__ __align__(16) uint32_t As[128][36];
    __shared__ __align__(16) uint32_t Bs[128][36];

    const int z = blockIdx.z;
    A += (long long)(z / zdA) * sA;
    W += (long long)(z % zmB) * sB;
    C += (long long)z * sC;

    const int tid  = threadIdx.x;
    const int warp = tid >> 5, lane = tid & 31;
    const int wm = warp >> 2;
    const int wn = warp & 3;
    const int g  = lane >> 2;
    const int tg = lane & 3;
    const int m0 = blockIdx.y * 128;
    const int n0 = blockIdx.x * 128;

    float acc[4][4][4];
#pragma unroll
    for (int mt = 0; mt < 4; mt++)
#pragma unroll
        for (int nt = 0; nt < 4; nt++)
#pragma unroll
            for (int r = 0; r < 4; r++) acc[mt][nt][r] = 0.f;

    for (int k0 = 0; k0 < K; k0 += 32) {
#pragma unroll
        for (int it = 0; it < 4; it++) {
            int idx = tid + it * 256;
            int r = idx >> 3;
            int c = (idx & 7) << 2;
            float4 v = *reinterpret_cast<const float4*>(A + (size_t)(m0 + r) * K + k0 + c);
            As[r][c + 0] = f2tf(v.x); As[r][c + 1] = f2tf(v.y);
            As[r][c + 2] = f2tf(v.z); As[r][c + 3] = f2tf(v.w);
        }
#pragma unroll
        for (int it = 0; it < 4; it++) {
            int idx = tid + it * 256;
            int r = idx >> 3;
            int c = (idx & 7) << 2;
            int n = n0 + r;
            float4 v = make_float4(0.f, 0.f, 0.f, 0.f);
            if (n < N) v = *reinterpret_cast<const float4*>(W + (size_t)n * K + k0 + c);
            Bs[r][c + 0] = f2tf(v.x); Bs[r][c + 1] = f2tf(v.y);
            Bs[r][c + 2] = f2tf(v.z); Bs[r][c + 3] = f2tf(v.w);
        }
        __syncthreads();

#pragma unroll
        for (int ks = 0; ks < 4; ks++) {
            const int kc = ks * 8 + tg;
            uint32_t af[4][4], bf[4][2];
#pragma unroll
            for (int mt = 0; mt < 4; mt++) {
                int rb = wm * 64 + mt * 16 + g;
                af[mt][0] = As[rb][kc];       af[mt][1] = As[rb + 8][kc];
                af[mt][2] = As[rb][kc + 4];   af[mt][3] = As[rb + 8][kc + 4];
            }
#pragma unroll
            for (int nt = 0; nt < 4; nt++) {
                int nb = wn * 32 + nt * 8 + g;
                bf[nt][0] = Bs[nb][kc];       bf[nt][1] = Bs[nb][kc + 4];
            }
#pragma unroll
            for (int mt = 0; mt < 4; mt++)
#pragma unroll
                for (int nt = 0; nt < 4; nt++)
                    MMA_TF32(acc[mt][nt], af[mt][0], af[mt][1], af[mt][2], af[mt][3],
                             bf[nt][0], bf[nt][1]);
        }
        __syncthreads();
    }

#pragma unroll
    for (int mt = 0; mt < 4; mt++) {
        int row = m0 + wm * 64 + mt * 16 + g;
#pragma unroll
        for (int nt = 0; nt < 4; nt++) {
            int col = n0 + wn * 32 + nt * 8 + (tg << 1);
            if (col < N) {
                float2 bv = make_float2(0.f, 0.f);
                if (bias) bv = *reinterpret_cast<const float2*>(bias + col);
                float2 v0 = make_float2(acc[mt][nt][0] + bv.x, acc[mt][nt][1] + bv.y);
                float2 v1 = make_float2(acc[mt][nt][2] + bv.x, acc[mt][nt][3] + bv.y);
                *reinterpret_cast<float2*>(C + (size_t)row * N + col) = v0;
                *reinterpret_cast<float2*>(C + (size_t)(row + 8) * N + col) = v1;
            }
        }
    }
}

// ---------------- RMSNorm (in-place), one block per row --------------------
__global__ void __launch_bounds__(256) rmsnorm_k(float* __restrict__ x,
                                                 const float* __restrict__ w, int D)
{
    const int row = blockIdx.x;
    float* xr = x + (size_t)row * D;
    float ss = 0.f;
    for (int i = threadIdx.x; i < D; i += 256) { float v = xr[i]; ss = fmaf(v, v, ss); }
    __shared__ float red[8];
#pragma unroll
    for (int d = 16; d; d >>= 1) ss += __shfl_xor_sync(0xffffffffu, ss, d);
    if ((threadIdx.x & 31) == 0) red[threadIdx.x >> 5] = ss;
    __syncthreads();
    if (threadIdx.x == 0) {
        float t = 0.f;
#pragma unroll
        for (int i = 0; i < 8; i++) t += red[i];
        red[0] = t;
    }
    __syncthreads();
    const float r = rsqrtf(red[0] / (float)D + 1e-6f);
    for (int i = threadIdx.x; i < D; i += 256) xr[i] = w[i] * (xr[i] * r);
}

// ---------------- RoPE tables (fp64 trig for range safety) ------------------
__global__ void rope_tab_k(float* __restrict__ ct, float* __restrict__ st)
{
    const int pos = blockIdx.x;
    const int j = threadIdx.x;
    double inv = pow(10000.0, -((double)j) / 32.0);
    float ang = (float)pos * (float)inv;
    float c = (float)cos((double)ang);
    float s = (float)sin((double)ang);
    ct[pos * 64 + j] = c; ct[pos * 64 + j + 32] = c;
    st[pos * 64 + j] = s; st[pos * 64 + j + 32] = s;
}

// ---------------- kv split: rmsnorm first 512, rope last 64 -----------------
__global__ void __launch_bounds__(256) kvprep_k(
    const float* __restrict__ kvf, const float* __restrict__ w,
    float* __restrict__ kvn, float* __restrict__ kpe,
    const float* __restrict__ ct, const float* __restrict__ st)
{
    const int row = blockIdx.x;
    const float* xr = kvf + (size_t)row * 576;
    float ss = 0.f;
    for (int i = threadIdx.x; i < 512; i += 256) { float v = xr[i]; ss = fmaf(v, v, ss); }
    __shared__ float red[8];
#pragma unroll
    for (int d = 16; d; d >>= 1) ss += __shfl_xor_sync(0xffffffffu, ss, d);
    if ((threadIdx.x & 31) == 0) red[threadIdx.x >> 5] = ss;
    __syncthreads();
    if (threadIdx.x == 0) {
        float t = 0.f;
#pragma unroll
        for (int i = 0; i < 8; i++) t += red[i];
        red[0] = t;
    }
    __syncthreads();
    const float r = rsqrtf(red[0] / 512.f + 1e-6f);
    for (int i = threadIdx.x; i < 512; i += 256)
        kvn[(size_t)row * 512 + i] = w[i] * (xr[i] * r);

    if (threadIdx.x < 32) {
        const int j = threadIdx.x;
        const int pos = row & (S_ - 1);
        float c = ct[pos * 64 + j], s = st[pos * 64 + j];
        float x1 = xr[512 + j], x2 = xr[544 + j];
        kpe[(size_t)row * 64 + j]      = x1 * c - x2 * s;
        kpe[(size_t)row * 64 + 32 + j] = x2 * c + x1 * s;
    }
}

// ---------------- rope on q_pe slice of each head (in-place) ----------------
__global__ void __launch_bounds__(256) ropeq_k(float* __restrict__ q,
                                               const float* __restrict__ ct,
                                               const float* __restrict__ st)
{
    const int idx = blockIdx.x * 256 + threadIdx.x;
    const int row = idx >> 9;
    const int h = (idx >> 5) & 15;
    const int j = idx & 31;
    const int pos = row & (S_ - 1);
    float* p = q + (size_t)row * 3072 + h * 192 + 128;
    float c = ct[pos * 64 + j], s = st[pos * 64 + j];
    float x1 = p[j], x2 = p[j + 32];
    p[j]      = x1 * c - x2 * s;
    p[j + 32] = x2 * c + x1 * s;
}

// ---------------- flash attention (absorbed MLA) on tensor cores ------------
// qk-dim 192 (128 k_abs + 64 k_pe), v-dim 128; tf32 mma m16n8k8, fp32 softmax.
// grid (32, 16, 2); 256 threads = 8 warps: wm=warp>>1 (16 rows), wn=warp&1.
// Score warp tile 16x32 (4 n-tiles); PV warp tile 16x64 (8 n-tiles).
// smem strides: 196 and 68 are ==4 mod 32 -> fragment LDS conflict-free.
__global__ void __launch_bounds__(256) attn_k(
    const float* __restrict__ Q,    // [4096, 3072]
    const float* __restrict__ KV,   // [32][2048][256]: k_abs | v_abs
    const float* __restrict__ Kpe,  // [4096, 64]
    const int*   __restrict__ msk,  // [2, 2048]
    float* __restrict__ Out)        // [4096, 2048]
{
    const int qb = blockIdx.x, h = blockIdx.y, b = blockIdx.z;
    const int tid = threadIdx.x;
    const int warp = tid >> 5, lane = tid & 31;
    const int wm = warp >> 1, wn = warp & 1;
    const int g = lane >> 2, tg = lane & 3;

    extern __shared__ uint32_t smu[];
    uint32_t* sQ  = smu;                 // [64][196] tf32
    uint32_t* sK  = sQ + 64 * 196;       // [64][196] tf32
    uint32_t* sVT = sK + 64 * 196;       // [128][68] tf32 (V transposed)
    uint32_t* sP  = sVT + 128 * 68;      // [64][68]  tf32
    float* sM = (float*)(sP + 64 * 68);  // [2][64] row-max partials
    float* sS = sM + 128;                // [2][64] row-sum partials

    const int s0 = qb * 64;
    const float* Qb = Q + (size_t)(b * 2048 + s0) * 3072 + h * 192;
    for (int idx = tid; idx < 64 * 48; idx += 256) {
        int r = idx / 48, c4 = idx % 48;
        float4 v = *reinterpret_cast<const float4*>(Qb + (size_t)r * 3072 + c4 * 4);
        uint32_t* d = sQ + r * 196 + c4 * 4;
        d[0] = f2tf(v.x); d[1] = f2tf(v.y); d[2] = f2tf(v.z); d[3] = f2tf(v.w);
    }

    const float scale = 0.07216878364870322f;  // 1/sqrt(192)
    const int r1 = wm * 16 + g, r2 = r1 + 8;   // local rows this thread owns
    const int sg1 = s0 + r1, sg2 = s0 + r2;    // global q positions

    float m1 = -3.0e38f, m2 = -3.0e38f, l1 = 0.f, l2 = 0.f;
    float o[8][4];
#pragma unroll
    for (int nt = 0; nt < 8; nt++)
#pragma unroll
        for (int r = 0; r < 4; r++) o[nt][r] = 0.f;

    const int* mrow = msk + (size_t)b * 2048;

    for (int kt = 0; kt <= qb; kt++) {
        __syncthreads();  // protect smem reuse vs previous iteration's reads
        const float* KVb = KV + ((size_t)(b * 16 + h) * 2048 + kt * 64) * 256;
        for (int idx = tid; idx < 64 * 64; idx += 256) {
            int r = idx >> 6, c4 = idx & 63;
            float4 v = *reinterpret_cast<const float4*>(KVb + (size_t)r * 256 + c4 * 4);
            if (c4 < 32) {
                uint32_t* d = sK + r * 196 + c4 * 4;
                d[0] = f2tf(v.x); d[1] = f2tf(v.y); d[2] = f2tf(v.z); d[3] = f2tf(v.w);
            } else {
                int vc = (c4 - 32) * 4;
                sVT[(vc + 0) * 68 + r] = f2tf(v.x);
                sVT[(vc + 1) * 68 + r] = f2tf(v.y);
                sVT[(vc + 2) * 68 + r] = f2tf(v.z);
                sVT[(vc + 3) * 68 + r] = f2tf(v.w);
            }
        }
        const float* Kpb = Kpe + (size_t)(b * 2048 + kt * 64) * 64;
        for (int idx = tid; idx < 64 * 16; idx += 256) {
            int r = idx >> 4, c4 = idx & 15;
            float4 v = *reinterpret_cast<const float4*>(Kpb + (size_t)r * 64 + c4 * 4);
            uint32_t* d = sK + r * 196 + 128 + c4 * 4;
            d[0] = f2tf(v.x); d[1] = f2tf(v.y); d[2] = f2tf(v.z); d[3] = f2tf(v.w);
        }
        __syncthreads();

        // ---- scores: 16x32 per warp over 192-dim contraction ----
        float sc[4][4];
#pragma unroll
        for (int nt = 0; nt < 4; nt++)
#pragma unroll
            for (int r = 0; r < 4; r++) sc[nt][r] = 0.f;

#pragma unroll
        for (int ks = 0; ks < 24; ks++) {
            const int kc = ks * 8 + tg;
            const uint32_t* aq = sQ + r1 * 196 + kc;
            uint32_t a0 = aq[0], a1 = aq[8 * 196], a2 = aq[4], a3 = aq[8 * 196 + 4];
#pragma unroll
            for (int nt = 0; nt < 4; nt++) {
                const uint32_t* bk = sK + (wn * 32 + nt * 8 + g) * 196 + kc;
                MMA_TF32(sc[nt], a0, a1, a2, a3, bk[0], bk[4]);
            }
        }

        // ---- scale + mask + row max ----
        const bool diag = (kt == qb);
        float tm1 = -3.0e38f, tm2 = -3.0e38f;
#pragma unroll
        for (int nt = 0; nt < 4; nt++) {
            int t0 = kt * 64 + wn * 32 + nt * 8 + 2 * tg, t1 = t0 + 1;
            int mv0 = mrow[t0], mv1 = mrow[t1];
            float v0 = sc[nt][0] * scale; if ((diag && t0 > sg1) || mv0 == 0) v0 = -1e15f;
            float v1 = sc[nt][1] * scale; if ((diag && t1 > sg1) || mv1 == 0) v1 = -1e15f;
            float v2 = sc[nt][2] * scale; if ((diag && t0 > sg2) || mv0 == 0) v2 = -1e15f;
            float v3 = sc[nt][3] * scale; if ((diag && t1 > sg2) || mv1 == 0) v3 = -1e15f;
            sc[nt][0] = v0; sc[nt][1] = v1; sc[nt][2] = v2; sc[nt][3] = v3;
            tm1 = fmaxf(tm1, fmaxf(v0, v1));
            tm2 = fmaxf(tm2, fmaxf(v2, v3));
        }
        tm1 = fmaxf(tm1, __shfl_xor_sync(0xffffffffu, tm1, 1));
        tm1 = fmaxf(tm1, __shfl_xor_sync(0xffffffffu, tm1, 2));
        tm2 = fmaxf(tm2, __shfl_xor_sync(0xffffffffu, tm2, 1));
        tm2 = fmaxf(tm2, __shfl_xor_sync(0xffffffffu, tm2, 2));
        if (tg == 0) { sM[wn * 64 + r1] = tm1; sM[wn * 64 + r2] = tm2; }
        __syncthreads();

        float nm1 = fmaxf(m1, fmaxf(sM[r1], sM[64 + r1]));
        float nm2 = fmaxf(m2, fmaxf(sM[r2], sM[64 + r2]));
        float al1 = expf(m1 - nm1), al2 = expf(m2 - nm2);
        m1 = nm1; m2 = nm2;

        // ---- exp + P store (tf32) + row sum ----
        float ls1 = 0.f, ls2 = 0.f;
#pragma unroll
        for (int nt = 0; nt < 4; nt++) {
            float p0 = expf(sc[nt][0] - nm1);
            float p1 = expf(sc[nt][1] - nm1);
            float p2 = expf(sc[nt][2] - nm2);
            float p3 = expf(sc[nt][3] - nm2);
            ls1 += p0 + p1; ls2 += p2 + p3;
            int jc = wn * 32 + nt * 8 + 2 * tg;
            sP[r1 * 68 + jc]     = f2tf(p0);
            sP[r1 * 68 + jc + 1] = f2tf(p1);
            sP[r2 * 68 + jc]     = f2tf(p2);
            sP[r2 * 68 + jc + 1] = f2tf(p3);
        }
        ls1 += __shfl_xor_sync(0xffffffffu, ls1, 1);
        ls1 += __shfl_xor_sync(0xffffffffu, ls1, 2);
        ls2 += __shfl_xor_sync(0xffffffffu, ls2, 1);
        ls2 += __shfl_xor_sync(0xffffffffu, ls2, 2);
        if (tg == 0) { sS[wn * 64 + r1] = ls1; sS[wn * 64 + r2] = ls2; }
        __syncthreads();

        l1 = l1 * al1 + sS[r1] + sS[64 + r1];
        l2 = l2 * al2 + sS[r2] + sS[64 + r2];

        // ---- O rescale + PV: 16x64 per warp over 64-dim contraction ----
#pragma unroll
        for (int nt = 0; nt < 8; nt++) {
            o[nt][0] *= al1; o[nt][1] *= al1; o[nt][2] *= al2; o[nt][3] *= al2;
        }
#pragma unroll
        for (int ks = 0; ks < 8; ks++) {
            const int kc = ks * 8 + tg;
            const uint32_t* ap = sP + r1 * 68 + kc;
            uint32_t a0 = ap[0], a1 = ap[8 * 68], a2 = ap[4], a3 = ap[8 * 68 + 4];
#pragma unroll
            for (int nt = 0; nt < 8; nt++) {
                const uint32_t* bv = sVT + (wn * 64 + nt * 8 + g) * 68 + kc;
                MMA_TF32(o[nt], a0, a1, a2, a3, bv[0], bv[4]);
            }
        }
    }

    // ---- epilogue ----
    const float i1 = 1.f / l1, i2 = 1.f / l2;
    float* orow1 = Out + (size_t)(b * 2048 + sg1) * 2048 + h * 128;
    float* orow2 = Out + (size_t)(b * 2048 + sg2) * 2048 + h * 128;
#pragma unroll
    for (int nt = 0; nt < 8; nt++) {
        int c = wn * 64 + nt * 8 + 2 * tg;
        *reinterpret_cast<float2*>(orow1 + c) = make_float2(o[nt][0] * i1, o[nt][1] * i1);
        *reinterpret_cast<float2*>(orow2 + c) = make_float2(o[nt][2] * i2, o[nt][3] * i2);
    }
}

// ------------------------------- host side ---------------------------------
extern "C" void kernel_launch(void* const* d_in, const int* in_sizes, int n_in,
                              void* d_out, int out_size)
{
    (void)in_sizes; (void)n_in; (void)out_size;
    const float* x        = (const float*)d_in[0];
    const int*   mask     = (const int*)  d_in[1];
    const float* wq_a_w   = (const float*)d_in[2];
    const float* wq_a_b   = (const float*)d_in[3];
    const float* q_norm_w = (const float*)d_in[4];
    const float* wq_b_w   = (const float*)d_in[5];
    const float* wq_b_b   = (const float*)d_in[6];
    const float* wkv_a_w  = (const float*)d_in[7];
    const float* wkv_a_b  = (const float*)d_in[8];
    const float* kv_norm_w= (const float*)d_in[9];
    const float* wkv_b_w  = (const float*)d_in[10];
    const float* wo_w     = (const float*)d_in[11];
    const float* wo_b     = (const float*)d_in[12];
    float* out = (float*)d_out;

    float *qa, *q, *kvf, *kvn, *kpe, *kvab, *att, *ct, *st;
    cudaGetSymbolAddress((void**)&qa,   g_qa);
    cudaGetSymbolAddress((void**)&q,    g_q);
    cudaGetSymbolAddress((void**)&kvf,  g_kvf);
    cudaGetSymbolAddress((void**)&kvn,  g_kvn);
    cudaGetSymbolAddress((void**)&kpe,  g_kpe);
    cudaGetSymbolAddress((void**)&kvab, g_kvab);
    cudaGetSymbolAddress((void**)&att,  g_att);
    cudaGetSymbolAddress((void**)&ct,   g_cos);
    cudaGetSymbolAddress((void**)&st,   g_sin);

    rope_tab_k<<<S_, 32>>>(ct, st);

    // q_a = x @ wq_a^T + b   [4096,2048]x[1536,2048]
    { dim3 g(QL_ / 128, ROWS_ / 128, 1);
      sgemm_bias<<<g, 256>>>(x, wq_a_w, wq_a_b, qa, ROWS_, QL_, H_, 1, 0, 1, 0, 0); }
    rmsnorm_k<<<ROWS_, 256>>>(qa, q_norm_w, QL_);
    // q = q_a @ wq_b^T + b   [4096,1536]x[3072,1536]
    { dim3 g((NH_ * QKH_) / 128, ROWS_ / 128, 1);
      sgemm_bias<<<g, 256>>>(qa, wq_b_w, wq_b_b, q, ROWS_, NH_ * QKH_, QL_, 1, 0, 1, 0, 0); }
    // kv_full = x @ wkv_a^T + b   [4096,2048]x[576,2048]
    { dim3 g((KVL_ + ROPE_ + 127) / 128, ROWS_ / 128, 1);
      sgemm_bias<<<g, 256>>>(x, wkv_a_w, wkv_a_b, kvf, ROWS_, KVL_ + ROPE_, H_, 1, 0, 1, 0, 0); }
    kvprep_k<<<ROWS_, 256>>>(kvf, kv_norm_w, kvn, kpe, ct, st);
    ropeq_k<<<(ROWS_ * NH_ * 32) / 256, 256>>>(q, ct, st);

    // absorbed K/V: per (b,h): kvab[z] = kvn[b] (2048x512) @ wkv_b[h] (256x512)^T
    { dim3 g(256 / 128, S_ / 128, B_ * NH_);
      sgemm_bias<<<g, 256>>>(kvn, wkv_b_w, nullptr, kvab, S_, 256, KVL_,
                             NH_, (long long)S_ * KVL_,
                             NH_, 256LL * KVL_,
                             (long long)S_ * 256); }

    // flash attention (tensor-core)
    const int smem = (64 * 196 * 2 + 128 * 68 + 64 * 68) * 4 + 2 * 128 * 4;  // 153,600 B
    cudaFuncSetAttribute(attn_k, cudaFuncAttributeMaxDynamicSharedMemorySize, smem);
    attn_k<<<dim3(S_ / 64, NH_, B_), 256, smem>>>(q, kvab, kpe, mask, att);

    // out = att @ wo^T + b   [4096,2048]x[2048,2048]
    { dim3 g(H_ / 128, ROWS_ / 128, 1);
      sgemm_bias<<<g, 256>>>(att, wo_w, wo_b, out, ROWS_, H_, NH_ * VD_, 1, 0, 1, 0, 0); }
}